// round 14
// baseline (speedup 1.0000x reference)
#include <cuda_runtime.h>
#include <cstdint>

#define CRF_B 512
#define CRF_S 512
#define CRF_T 64

// Per-batch partial results + completion ticket (device scratch; no allocs).
__device__ float    g_dpart[CRF_B];
__device__ float    g_npart[CRF_B];
__device__ unsigned g_ticket;   // zero-init; last CTA resets it each run

typedef unsigned long long u64;

// ---- packed f32x2 helpers (sm_100+ PTX) ----
__device__ __forceinline__ u64 ffma2(u64 a, u64 b, u64 c) {
    u64 d;
    asm("fma.rn.f32x2 %0, %1, %2, %3;" : "=l"(d) : "l"(a), "l"(b), "l"(c));
    return d;
}
__device__ __forceinline__ u64 fadd2(u64 a, u64 b) {
    u64 d;
    asm("add.rn.f32x2 %0, %1, %2;" : "=l"(d) : "l"(a), "l"(b));
    return d;
}
__device__ __forceinline__ u64 pack2(float x, float y) {
    u64 d;
    asm("mov.b64 %0, {%1, %2};" : "=l"(d) : "f"(x), "f"(y));
    return d;
}
__device__ __forceinline__ float2 unpack2(u64 a) {
    float2 r;
    asm("mov.b64 {%0, %1}, %2;" : "=f"(r.x), "=f"(r.y) : "l"(a));
    return r;
}
__device__ __forceinline__ void barsync(int id) {
    asm volatile("bar.sync %0, 64;" :: "r"(id) : "memory");
}

// Warp-uniform layout detection (ballot => uniform, no global state).
__device__ __forceinline__ int detect_mshift(const void* mask, int l) {
    const unsigned* mw = (const unsigned*)mask;
    unsigned bad = ((mw[l] | mw[l + 32]) & 0xFFFFFF00u) ? 1u : 0u;
    return __ballot_sync(0xffffffffu, bad) ? 0 : 2;   // u8 : i32
}
__device__ __forceinline__ int detect_tshift(const void* tags, int l) {
    const unsigned* tw = (const unsigned*)tags;
    unsigned odd = tw[2 * l + 1] ? 1u : 0u;
    return __ballot_sync(0xffffffffu, odd) ? 0 : 1;   // i32 : i64
}

// ============================================================================
// R14: TWO warps per batch (j-split). 256 blocks x 160 threads.
//   Warps 0-3: forward; warp pair (2q, 2q+1) handles batch 2*blockIdx.x + q.
//     Warp u of a pair owns output states j = 32u + l (ONE state per lane):
//     32 FFMA2 per step per warp (halves the per-warp fma issue stream), E in
//     registers (32 x f32x2 per lane), p exchanged via smem floats + ONE named
//     barrier (bar.sync id,64) per step.
//   Warp 4: numerator for the block's 2 batches.
//   Last CTA: deterministic final reduction.
// Exp-domain recurrence; exact power-of-2 renorm every 4 steps derived from
// the exponent of p[state 0] (broadcast load, identical in both warps).
// ============================================================================
__global__ void __launch_bounds__(160, 1) crf_main(
    const float* __restrict__ logits,
    const void* __restrict__ tagsv,
    const void* __restrict__ maskv,
    const float* __restrict__ trans,
    const float* __restrict__ startT,
    const float* __restrict__ endT,
    float* __restrict__ out)
{
    __shared__ __align__(16) float psm[2][2][CRF_T];  // [batch][pingpong][state]
    __shared__ float xch[2][2];                       // cross-warp scalar exchange
    __shared__ float rbuf[256];
    __shared__ int   do_red;

    const int tid = threadIdx.x;
    const int w   = tid >> 5;
    const int l   = tid & 31;

    const int msh = detect_mshift(maskv, l);

    if (w == 4) {
        // ---------------- Numerator warp ----------------
        const int tsh = detect_tshift(tagsv, l);
        const int*           tg  = (const int*)tagsv;
        const unsigned char* mkp = (const unsigned char*)maskv;

        for (int q = 0; q < 2; q++) {
            const int    b  = blockIdx.x * 2 + q;
            const float* lg = logits + (size_t)b * (CRF_S * CRF_T);
            const size_t eb = (size_t)b * CRF_S;

            float acc = 0.0f;
            int   cnt = 0;
            for (int s = l; s < CRF_S; s += 32) {
                const int  t = tg[(eb + s) << tsh];
                const bool m = (mkp[(eb + s) << msh] != 0);
                if (m) {
                    cnt++;
                    if (s < CRF_S - 1) acc += lg[(size_t)s * CRF_T + t];
                    if (s >= 1)        acc += trans[tg[(eb + s - 1) << tsh] * CRF_T + t];
                }
            }
#pragma unroll
            for (int o = 16; o; o >>= 1) {
                acc += __shfl_xor_sync(0xffffffffu, acc, o);
                cnt += __shfl_xor_sync(0xffffffffu, cnt, o);
            }
            if (l == 0) {
                acc += startT[tg[eb << tsh]];
                const int lt = tg[(eb + cnt - 1) << tsh];
                acc += endT[lt];
                if (mkp[(eb + CRF_S - 1) << msh]) acc += lg[(size_t)(CRF_S - 1) * CRF_T + lt];
                g_npart[b] = acc;
            }
        }
    } else {
        // ---------------- Forward warp pair ----------------
        const int bl  = w >> 1;          // batch slot in block (0/1)
        const int u   = w & 1;           // half index (0: states 0-31, 1: 32-63)
        const int b   = blockIdx.x * 2 + bl;
        const int j   = 32 * u + l;      // this lane's output state
        const int bid = 1 + bl;          // named barrier id for this batch

        // E pairs along i for this lane's single column j: 32 u64 (64 regs).
        u64 EA[32];
#pragma unroll
        for (int k = 0; k < 32; k++) {
            EA[k] = pack2(__expf(trans[(size_t)(2 * k) * CRF_T + j]),
                          __expf(trans[(size_t)(2 * k + 1) * CRF_T + j]));
        }

        const float*         lg = logits + (size_t)b * (CRF_S * CRF_T);
        const unsigned char* mk = (const unsigned char*)maskv + (((size_t)b * CRF_S) << msh);

        // All-ones-mask detection for this batch (warp-uniform via ballot).
        bool allm;
        {
            unsigned bad = 0u;
            for (int k = l; k < CRF_S; k += 32)
                bad |= (mk[(size_t)k << msh] == 0) ? 1u : 0u;
            allm = (__ballot_sync(0xffffffffu, bad) == 0u);
        }

        // init: alpha0 = start + logits[:,0,:]; exp-domain with offset C.
        float a = startT[j] + lg[j];
        float mx = a;
#pragma unroll
        for (int o = 16; o; o >>= 1) mx = fmaxf(mx, __shfl_xor_sync(0xffffffffu, mx, o));
        if (l == 0) xch[bl][u] = mx;
        barsync(bid);
        const float C0 = fmaxf(xch[bl][0], xch[bl][1]);
        float C = C0;
        float p = __expf(a - C);
        psm[bl][0][j] = p;

        // prologue: 4-deep scalar logits/mask FIFO + current-step exp.
        float f1 = lg[1 * CRF_T + j];
        float f2 = lg[2 * CRF_T + j];
        float f3 = lg[3 * CRF_T + j];
        float f4 = lg[4 * CRF_T + j];
        float f5 = lg[5 * CRF_T + j];
        unsigned char m2 = mk[(size_t)2 << msh];
        unsigned char m3 = mk[(size_t)3 << msh];
        unsigned char m4 = mk[(size_t)4 << msh];
        unsigned char m5 = mk[(size_t)5 << msh];
        float e = __expf(f1);
        unsigned char cm = mk[(size_t)1 << msh];
        barsync(bid);

        // One recurrence step; um (literal at call sites) folds mask logic.
        auto step = [&](int s, bool um, const float* srcf, float* dstf) {
            const ulonglong2* q2 = (const ulonglong2*)srcf;
            // 16 broadcast LDS.128; 32 FFMA2 in 4 depth-8 chains.
            u64 a0 = 0ull, a1 = 0ull, a2 = 0ull, a3 = 0ull;
            u64 qfirst = 0ull;               // {p[0], p[1]} — renorm source
#pragma unroll
            for (int m = 0; m < 16; m += 2) {
                ulonglong2 qa = q2[m];
                ulonglong2 qb = q2[m + 1];
                if (m == 0) qfirst = qa.x;
                a0 = ffma2(EA[2 * m],     qa.x, a0);
                a1 = ffma2(EA[2 * m + 1], qa.y, a1);
                a2 = ffma2(EA[2 * m + 2], qb.x, a2);
                a3 = ffma2(EA[2 * m + 3], qb.y, a3);
            }

            // FIFO rotate + clamped prefetch.
            const float head       = f2;
            const unsigned char mh = m2;
            f2 = f3;
            f3 = f4;
            f4 = f5;
            const int sp = (s + 5 < CRF_S) ? (s + 5) : (CRF_S - 1);
            f5 = lg[(size_t)sp * CRF_T + j];
            if (um) {
                m2 = m3; m3 = m4; m4 = m5;
                m5 = mk[(size_t)sp << msh];
            }
            const float ne = __expf(head);

            float2 sA = unpack2(fadd2(fadd2(a0, a1), fadd2(a2, a3)));
            const float pn = (sA.x + sA.y) * e;
            if (um) {
                if (cm) p = pn;              // mask: keep old alpha if 0
            } else {
                p = pn;
            }

            // Exact power-of-2 renorm every 4 steps. Scale from exponent of
            // p[state 0] (broadcast load low word) — identical in both warps.
            if ((s & 3) == 0) {
                const int ex = (int)((qfirst >> 23) & 255ull);
                const float scale = __int_as_float((254 - ex) << 23);  // 2^(127-ex)
                p *= scale;
                C += (float)(ex - 127) * 0.6931471805599453f;
            }

            dstf[j] = p;
            e = ne;
            if (um) cm = mh;
            barsync(bid);
        };

        // s = 1..510 in pairs (static ping-pong), tail s = 511.
        if (allm) {
            for (int s = 1; s < CRF_S - 1; s += 2) {
                step(s,     false, psm[bl][0], psm[bl][1]);
                step(s + 1, false, psm[bl][1], psm[bl][0]);
            }
            step(CRF_S - 1, false, psm[bl][0], psm[bl][1]);
        } else {
            for (int s = 1; s < CRF_S - 1; s += 2) {
                step(s,     true, psm[bl][0], psm[bl][1]);
                step(s + 1, true, psm[bl][1], psm[bl][0]);
            }
            step(CRF_S - 1, true, psm[bl][0], psm[bl][1]);
        }

        // denom = C + log(sum_j p_j * exp(end_j)); cross-warp combine.
        float v = p * __expf(endT[j]);
#pragma unroll
        for (int o = 16; o; o >>= 1) v += __shfl_xor_sync(0xffffffffu, v, o);
        if (l == 0) xch[bl][u] = v;
        barsync(bid);
        if (u == 0 && l == 0)
            g_dpart[b] = C + logf(xch[bl][0] + xch[bl][1]);
    }

    // ---- last CTA performs the final deterministic reduction ----
    __syncthreads();
    if (tid == 0) {
        __threadfence();
        unsigned t = atomicAdd(&g_ticket, 1u);
        do_red = (t == gridDim.x - 1);
    }
    __syncthreads();
    if (do_red) {
        __threadfence();
        float a = 0.0f;
        for (int i = tid; i < CRF_B; i += 160)     // fixed order per thread
            a += g_npart[i] - g_dpart[i];
        rbuf[tid] = a;
        if (tid < 96) rbuf[160 + tid] = 0.0f;
        __syncthreads();
        for (int o = 128; o; o >>= 1) {
            if (tid < o) rbuf[tid] += rbuf[tid + o];
            __syncthreads();
        }
        if (tid == 0) { out[0] = rbuf[0]; g_ticket = 0u; }
    }
}

extern "C" void kernel_launch(void* const* d_in, const int* in_sizes, int n_in,
                              void* d_out, int out_size)
{
    const float* logits = (const float*)d_in[0];
    const void*  tags   = d_in[1];
    const void*  mask   = d_in[2];
    const float* trans  = (const float*)d_in[3];
    const float* startT = (const float*)d_in[4];
    const float* endT   = (const float*)d_in[5];
    float*       out    = (float*)d_out;

    crf_main<<<CRF_B / 2, 160>>>(logits, tags, mask, trans, startT, endT, out);
}